// round 14
// baseline (speedup 1.0000x reference)
#include <cuda_runtime.h>
#include <cuda_bf16.h>

#define N_NODES    1000000
#define NUM_GRAPHS 1024

// Scratch — __device__ globals are ZERO-INITIALIZED at module load.
// Invariant: every kernel_launch call both starts AND ends with these zeroed
// (pool_kernel zeroes d_agg it consumed; out_kernel zeroes d_gsum),
// so no init kernel is needed and graph replays are deterministic.
__device__ float d_agg[N_NODES];      // per-node aggregated sum
__device__ float d_gsum[NUM_GRAPHS];  // per-graph sum of relu(agg)

// ---------------------------------------------------------------------------
// Per-block index-dtype detection. JAX with x64 disabled silently downcasts
// int64->int32: an int32 pair reinterpreted as u64 is >= 2^32 unless the hi
// index is 0; sampling 8 fixed words makes misdetection probability ~0 and
// every block reads the SAME bytes, so all blocks agree.
// ---------------------------------------------------------------------------
__device__ __forceinline__ int detect_is64(const void* edges) {
    const unsigned long long* p = (const unsigned long long*)edges;
    int is64 = 1;
    #pragma unroll
    for (int k = 0; k < 8; k++)
        if (__ldg(&p[k]) >= (1ull << 32)) is64 = 0;
    return is64;
}

// ---------------------------------------------------------------------------
// Edge scatter: agg[dst[e]] += x[src[e]].  4 edges/thread, block=512 — the
// measured optimum (231.8us @ L2=94.4%): 64M random lane-ops (32M gathers +
// 32M REDs) at ~1 L1tex wavefront / 32B L2 sector each IS the hardware
// floor. DO NOT TOUCH.
// edge_index layout: [2, E] row-major -> src = [0,E), dst = [E, 2E).
// ---------------------------------------------------------------------------
#define EDGE_BLOCK 512
__global__ void __launch_bounds__(EDGE_BLOCK) edge_kernel(
        const void* __restrict__ edge_ptr,
        const float* __restrict__ x,
        long long n_edges) {
    __shared__ int s_is64;
    if (threadIdx.x == 0) s_is64 = detect_is64(edge_ptr);
    __syncthreads();
    const int is64 = s_is64;

    long long t    = (long long)blockIdx.x * EDGE_BLOCK + threadIdx.x;
    long long base = t * 4;
    if (base >= n_edges) return;

    int s[4], d[4];
    if (is64) {
        const longlong2* src2 = (const longlong2*)edge_ptr;          // 2 idx / 16B
        const longlong2* dst2 = src2 + (n_edges >> 1);
        longlong2 a = __ldg(&src2[base >> 1]);
        longlong2 b = __ldg(&src2[(base >> 1) + 1]);
        longlong2 c = __ldg(&dst2[base >> 1]);
        longlong2 e = __ldg(&dst2[(base >> 1) + 1]);
        s[0] = (int)a.x; s[1] = (int)a.y; s[2] = (int)b.x; s[3] = (int)b.y;
        d[0] = (int)c.x; d[1] = (int)c.y; d[2] = (int)e.x; d[3] = (int)e.y;
    } else {
        const int4* src4 = (const int4*)edge_ptr;                    // 4 idx / 16B
        const int4* dst4 = (const int4*)((const int*)edge_ptr + n_edges);
        int4 a = __ldg(&src4[base >> 2]);
        int4 c = __ldg(&dst4[base >> 2]);
        s[0] = a.x; s[1] = a.y; s[2] = a.z; s[3] = a.w;
        d[0] = c.x; d[1] = c.y; d[2] = c.z; d[3] = c.w;
    }

    #pragma unroll
    for (int k = 0; k < 4; k++) {
        if (base + k < n_edges) {
            float xv = __ldg(&x[s[k]]);
            atomicAdd(&d_agg[d[k]], xv);   // result unused -> RED.E.ADD.F32
        }
    }
}

// ---------------------------------------------------------------------------
// ReLU + segmented SUM pool with warp-aggregated atomics. Counts are NOT
// accumulated here — out_kernel derives them by binary search on the sorted
// batch array. Fast path (warp entirely inside one graph, ~75% of warps):
// butterfly-reduce + 1 RED per warp. Each thread zeroes its d_agg slots
// (restores the zero-invariant).
// ---------------------------------------------------------------------------
#define NODES_PER_THREAD 8
__global__ void __launch_bounds__(256) pool_kernel(
        const void* __restrict__ batch_ptr,
        const void* __restrict__ edge_ptr) {   // edge_ptr: dtype detect only
    __shared__ int s_is64;
    if (threadIdx.x == 0) s_is64 = detect_is64(edge_ptr);
    __syncthreads();
    const int is64 = s_is64;

    long long t    = (long long)blockIdx.x * blockDim.x + threadIdx.x;
    long long base = t * NODES_PER_THREAD;
    const bool valid = (base < N_NODES);   // N_NODES % 8 == 0 -> full 8 if valid

    int   g[NODES_PER_THREAD];
    float h[NODES_PER_THREAD];
    float s_loc = 0.0f;

    if (valid) {
        #pragma unroll
        for (int j = 0; j < NODES_PER_THREAD / 4; j++) {
            float4 a = *(const float4*)&d_agg[base + 4*j];
            h[4*j] = a.x; h[4*j+1] = a.y; h[4*j+2] = a.z; h[4*j+3] = a.w;
        }
        // restore zero-invariant for the next call / graph replay
        #pragma unroll
        for (int j = 0; j < NODES_PER_THREAD / 4; j++)
            *(float4*)&d_agg[base + 4*j] = make_float4(0.f, 0.f, 0.f, 0.f);

        if (is64) {
            const longlong2* bp = (const longlong2*)batch_ptr;
            #pragma unroll
            for (int j = 0; j < NODES_PER_THREAD / 2; j++) {
                longlong2 v = __ldg(&bp[(base >> 1) + j]);
                g[2*j] = (int)v.x; g[2*j+1] = (int)v.y;
            }
        } else {
            const int4* bp = (const int4*)batch_ptr;
            #pragma unroll
            for (int j = 0; j < NODES_PER_THREAD / 4; j++) {
                int4 v = __ldg(&bp[(base >> 2) + j]);
                g[4*j] = v.x; g[4*j+1] = v.y; g[4*j+2] = v.z; g[4*j+3] = v.w;
            }
        }
        #pragma unroll
        for (int k = 0; k < NODES_PER_THREAD; k++)
            s_loc += h[k] > 0.0f ? h[k] : 0.0f;
    } else {
        #pragma unroll
        for (int k = 0; k < NODES_PER_THREAD; k++) g[k] = -1;
    }

    // ---- warp-uniform fast path: 1 RED per warp ----
    int g_first = __shfl_sync(0xffffffffu, g[0], 0);
    bool lane_uniform = valid && (g[0] == g[NODES_PER_THREAD - 1]) &&
                        (g[0] == g_first);
    if (__all_sync(0xffffffffu, lane_uniform)) {
        float s_w = s_loc;
        #pragma unroll
        for (int off = 16; off > 0; off >>= 1)
            s_w += __shfl_xor_sync(0xffffffffu, s_w, off);
        if ((threadIdx.x & 31) == 0)
            atomicAdd(&d_gsum[g_first], s_w);
        return;
    }

    // ---- slow path: per-thread segmented flush (sum only) ----
    if (!valid) return;
    int cur = g[0];
    float s = 0.0f;
    #pragma unroll
    for (int k = 0; k < NODES_PER_THREAD; k++) {
        float hv = h[k] > 0.0f ? h[k] : 0.0f;
        if (g[k] != cur) {
            atomicAdd(&d_gsum[cur], s);
            cur = g[k]; s = 0.0f;
        }
        s += hv;
    }
    atomicAdd(&d_gsum[cur], s);
}

// ---------------------------------------------------------------------------
// out[g] = (gsum[g] / max(count[g],1)) * W + b.
// count[g] = lower_bound(batch, g+1) - lower_bound(batch, g) via 20-step
// binary search on the SORTED batch array (no accumulation needed).
// Restores the zero-invariant on d_gsum. One 1024-thread block.
// ---------------------------------------------------------------------------
__device__ __forceinline__ long long lower_bound_batch(
        const void* batch, int is64, long long n, int key) {
    long long lo = 0, hi = n;
    while (lo < hi) {
        long long mid = (lo + hi) >> 1;
        int v = is64 ? (int)__ldg(&((const long long*)batch)[mid])
                     : __ldg(&((const int*)batch)[mid]);
        if (v < key) lo = mid + 1; else hi = mid;
    }
    return lo;
}

__global__ void out_kernel(const void* __restrict__ batch_ptr,
                           const void* __restrict__ edge_ptr,
                           const float* __restrict__ W,
                           const float* __restrict__ b,
                           float* __restrict__ out) {
    __shared__ int s_is64;
    if (threadIdx.x == 0) s_is64 = detect_is64(edge_ptr);
    __syncthreads();
    const int is64 = s_is64;

    int g = threadIdx.x;
    if (g < NUM_GRAPHS) {
        long long lo = lower_bound_batch(batch_ptr, is64, N_NODES, g);
        long long hi = lower_bound_batch(batch_ptr, is64, N_NODES, g + 1);
        float cnt = fmaxf((float)(hi - lo), 1.0f);
        float sum = d_gsum[g];
        out[g] = (sum / cnt) * __ldg(&W[0]) + __ldg(&b[0]);
        d_gsum[g] = 0.0f;              // restore zero-invariant
    }
}

extern "C" void kernel_launch(void* const* d_in, const int* in_sizes, int n_in,
                              void* d_out, int out_size) {
    const float* x     = (const float*)d_in[0];
    const float* W     = (const float*)d_in[1];
    const float* b     = (const float*)d_in[2];
    const void*  edges = d_in[3];
    const void*  batch = d_in[4];
    long long n_edges  = (long long)in_sizes[3] / 2;   // [2, E] -> E

    long long edge_threads = (n_edges + 3) / 4;
    edge_kernel<<<(int)((edge_threads + EDGE_BLOCK - 1) / EDGE_BLOCK),
                  EDGE_BLOCK>>>(edges, x, n_edges);

    long long pool_threads = (N_NODES + NODES_PER_THREAD - 1) / NODES_PER_THREAD;
    pool_kernel<<<(int)((pool_threads + 255) / 256), 256>>>(batch, edges);

    out_kernel<<<1, 1024>>>(batch, edges, W, b, (float*)d_out);
}

// round 17
// speedup vs baseline: 1.0419x; 1.0419x over previous
#include <cuda_runtime.h>
#include <cuda_bf16.h>

#define N_NODES    1000000
#define NUM_GRAPHS 1024

// Scratch — __device__ globals are ZERO-INITIALIZED at module load.
// Invariant: every kernel_launch call both starts AND ends with these zeroed
// (pool_kernel zeroes d_agg it consumed; out_kernel zeroes d_gsum/d_gcnt),
// so no init kernel is needed and graph replays are deterministic.
__device__ float d_agg[N_NODES];      // per-node aggregated sum
__device__ float d_gsum[NUM_GRAPHS];  // per-graph sum of relu(agg)
__device__ float d_gcnt[NUM_GRAPHS];  // per-graph node count

// ---------------------------------------------------------------------------
// Per-block index-dtype detection. JAX with x64 disabled silently downcasts
// int64->int32: an int32 pair reinterpreted as u64 is >= 2^32 unless the hi
// index is 0; sampling 8 fixed words makes misdetection probability ~0 and
// every block reads the SAME bytes, so all blocks agree.
// ---------------------------------------------------------------------------
__device__ __forceinline__ int detect_is64(const void* edges) {
    const unsigned long long* p = (const unsigned long long*)edges;
    int is64 = 1;
    #pragma unroll
    for (int k = 0; k < 8; k++)
        if (__ldg(&p[k]) >= (1ull << 32)) is64 = 0;
    return is64;
}

// ---------------------------------------------------------------------------
// Edge scatter: agg[dst[e]] += x[src[e]].  4 edges/thread — measured at the
// LTS sector/atomic hardware floor (231.8us @ L2=94.4%): 64M random lane-ops
// (32M gathers + 32M REDs) at ~1 L1tex wavefront / 32B L2 sector each.
// Code shape frozen; block size is the one lever that has moved it
// (256->512: -4.4us). This round: 512->1024 (fewer per-block overheads,
// same occupancy: 28 regs -> 2 blocks/SM).
// edge_index layout: [2, E] row-major -> src = [0,E), dst = [E, 2E).
// ---------------------------------------------------------------------------
#define EDGE_BLOCK 1024
__global__ void __launch_bounds__(EDGE_BLOCK) edge_kernel(
        const void* __restrict__ edge_ptr,
        const float* __restrict__ x,
        long long n_edges) {
    __shared__ int s_is64;
    if (threadIdx.x == 0) s_is64 = detect_is64(edge_ptr);
    __syncthreads();
    const int is64 = s_is64;

    long long t    = (long long)blockIdx.x * EDGE_BLOCK + threadIdx.x;
    long long base = t * 4;
    if (base >= n_edges) return;

    int s[4], d[4];
    if (is64) {
        const longlong2* src2 = (const longlong2*)edge_ptr;          // 2 idx / 16B
        const longlong2* dst2 = src2 + (n_edges >> 1);
        longlong2 a = __ldg(&src2[base >> 1]);
        longlong2 b = __ldg(&src2[(base >> 1) + 1]);
        longlong2 c = __ldg(&dst2[base >> 1]);
        longlong2 e = __ldg(&dst2[(base >> 1) + 1]);
        s[0] = (int)a.x; s[1] = (int)a.y; s[2] = (int)b.x; s[3] = (int)b.y;
        d[0] = (int)c.x; d[1] = (int)c.y; d[2] = (int)e.x; d[3] = (int)e.y;
    } else {
        const int4* src4 = (const int4*)edge_ptr;                    // 4 idx / 16B
        const int4* dst4 = (const int4*)((const int*)edge_ptr + n_edges);
        int4 a = __ldg(&src4[base >> 2]);
        int4 c = __ldg(&dst4[base >> 2]);
        s[0] = a.x; s[1] = a.y; s[2] = a.z; s[3] = a.w;
        d[0] = c.x; d[1] = c.y; d[2] = c.z; d[3] = c.w;
    }

    #pragma unroll
    for (int k = 0; k < 4; k++) {
        if (base + k < n_edges) {
            float xv = __ldg(&x[s[k]]);
            atomicAdd(&d_agg[d[k]], xv);   // result unused -> RED.E.ADD.F32
        }
    }
}

// ---------------------------------------------------------------------------
// ReLU + segmented pool with WARP-AGGREGATED atomics (R12 winning shape,
// reverted verbatim). batch is SORTED. Each thread handles 8 contiguous
// nodes; a warp covers 256. ~75% of warps lie entirely inside one graph:
// fast path warp-reduces the sum and lane 0 issues 2 atomics per warp.
// Each thread also zeroes its d_agg slots (restores the zero-invariant).
// ---------------------------------------------------------------------------
#define NODES_PER_THREAD 8
__global__ void __launch_bounds__(256) pool_kernel(
        const void* __restrict__ batch_ptr,
        const void* __restrict__ edge_ptr) {   // edge_ptr: dtype detect only
    __shared__ int s_is64;
    if (threadIdx.x == 0) s_is64 = detect_is64(edge_ptr);
    __syncthreads();
    const int is64 = s_is64;

    long long t    = (long long)blockIdx.x * blockDim.x + threadIdx.x;
    long long base = t * NODES_PER_THREAD;
    const bool valid = (base < N_NODES);   // N_NODES % 8 == 0 -> full 8 if valid

    int   g[NODES_PER_THREAD];
    float h[NODES_PER_THREAD];
    float s_loc = 0.0f;

    if (valid) {
        #pragma unroll
        for (int j = 0; j < NODES_PER_THREAD / 4; j++) {
            float4 a = *(const float4*)&d_agg[base + 4*j];
            h[4*j] = a.x; h[4*j+1] = a.y; h[4*j+2] = a.z; h[4*j+3] = a.w;
        }
        // restore zero-invariant for the next call / graph replay
        #pragma unroll
        for (int j = 0; j < NODES_PER_THREAD / 4; j++)
            *(float4*)&d_agg[base + 4*j] = make_float4(0.f, 0.f, 0.f, 0.f);

        if (is64) {
            const longlong2* bp = (const longlong2*)batch_ptr;
            #pragma unroll
            for (int j = 0; j < NODES_PER_THREAD / 2; j++) {
                longlong2 v = __ldg(&bp[(base >> 1) + j]);
                g[2*j] = (int)v.x; g[2*j+1] = (int)v.y;
            }
        } else {
            const int4* bp = (const int4*)batch_ptr;
            #pragma unroll
            for (int j = 0; j < NODES_PER_THREAD / 4; j++) {
                int4 v = __ldg(&bp[(base >> 2) + j]);
                g[4*j] = v.x; g[4*j+1] = v.y; g[4*j+2] = v.z; g[4*j+3] = v.w;
            }
        }
        #pragma unroll
        for (int k = 0; k < NODES_PER_THREAD; k++)
            s_loc += h[k] > 0.0f ? h[k] : 0.0f;
    } else {
        #pragma unroll
        for (int k = 0; k < NODES_PER_THREAD; k++) g[k] = -1;
    }

    // ---- warp-uniform fast path ----
    int g_first = __shfl_sync(0xffffffffu, g[0], 0);
    bool lane_uniform = valid && (g[0] == g[NODES_PER_THREAD - 1]) &&
                        (g[0] == g_first);
    if (__all_sync(0xffffffffu, lane_uniform)) {
        // whole warp (256 nodes) in one graph: butterfly-reduce sum
        float s_w = s_loc;
        #pragma unroll
        for (int off = 16; off > 0; off >>= 1)
            s_w += __shfl_xor_sync(0xffffffffu, s_w, off);
        if ((threadIdx.x & 31) == 0) {
            atomicAdd(&d_gsum[g_first], s_w);
            atomicAdd(&d_gcnt[g_first], 32.0f * NODES_PER_THREAD);
        }
        return;
    }

    // ---- slow path: per-thread segmented flush ----
    if (!valid) return;
    int cur = g[0];
    float s = 0.0f, c = 0.0f;
    #pragma unroll
    for (int k = 0; k < NODES_PER_THREAD; k++) {
        float hv = h[k] > 0.0f ? h[k] : 0.0f;
        if (g[k] != cur) {
            atomicAdd(&d_gsum[cur], s);
            atomicAdd(&d_gcnt[cur], c);
            cur = g[k]; s = 0.0f; c = 0.0f;
        }
        s += hv; c += 1.0f;
    }
    atomicAdd(&d_gsum[cur], s);
    atomicAdd(&d_gcnt[cur], c);
}

// ---------------------------------------------------------------------------
// out[g] = (gsum[g] / max(gcnt[g],1)) * W + b; then restore zero-invariant.
// Launch boundary provides all ordering — no fences. Single 1024-thread block.
// ---------------------------------------------------------------------------
__global__ void out_kernel(const float* __restrict__ W,
                           const float* __restrict__ b,
                           float* __restrict__ out) {
    int g = threadIdx.x;
    if (g < NUM_GRAPHS) {
        float sum = d_gsum[g];
        float cnt = fmaxf(d_gcnt[g], 1.0f);
        out[g] = (sum / cnt) * __ldg(&W[0]) + __ldg(&b[0]);
        d_gsum[g] = 0.0f;
        d_gcnt[g] = 0.0f;
    }
}

extern "C" void kernel_launch(void* const* d_in, const int* in_sizes, int n_in,
                              void* d_out, int out_size) {
    const float* x     = (const float*)d_in[0];
    const float* W     = (const float*)d_in[1];
    const float* b     = (const float*)d_in[2];
    const void*  edges = d_in[3];
    const void*  batch = d_in[4];
    long long n_edges  = (long long)in_sizes[3] / 2;   // [2, E] -> E

    long long edge_threads = (n_edges + 3) / 4;
    edge_kernel<<<(int)((edge_threads + EDGE_BLOCK - 1) / EDGE_BLOCK),
                  EDGE_BLOCK>>>(edges, x, n_edges);

    long long pool_threads = (N_NODES + NODES_PER_THREAD - 1) / NODES_PER_THREAD;
    pool_kernel<<<(int)((pool_threads + 255) / 256), 256>>>(batch, edges);

    out_kernel<<<1, 1024>>>(W, b, (float*)d_out);
}